// round 9
// baseline (speedup 1.0000x reference)
#include <cuda_runtime.h>
#include <cuda_bf16.h>

#define N 8192
#define F 64
#define TILES 32           // sorted key tiles of 256
#define CHN 1024           // scan chunks
#define CSZ 8              // ranks per chunk
#define NBLK 128
#define NTHR 256

// ---------------- scratch (no allocations allowed) ----------------
__device__ float g_ltg[N * F];
__device__ float g_ssrc[N];
__device__ float g_P[N];   // exp(s_src)
__device__ float g_p[N];   // exp(0.2 * s_src)
__device__ float g_Qs[N];  // exp(s_dst)
__device__ float g_qs[N];  // exp(0.2 * s_dst)
__device__ float g_sdst[N];
__device__ unsigned long long g_key[N];           // (sortable(sdst)<<32)|idx — unique
__device__ unsigned long long g_tkey[TILES][256]; // per-tile sorted keys
__device__ int   g_perm[N];                       // perm[rank] = original index
__device__ float g_sorted[N];                     // sdst ascending
__device__ double g_ctq[72][CHN];                 // chunk totals (q side), row 64 = scalar
__device__ double g_ctQ[72][CHN];
__device__ double g_coq[72][CHN];                 // exclusive chunk offsets
__device__ double g_coQ[72][CHN];
__device__ double g_totq[72];
__device__ double g_totQ[72];
__device__ float g_SufQ[(N + 1) * F];
__device__ float g_Preq[(N + 1) * F];
__device__ float g_SufQs[N + 1];
__device__ float g_Preqs[N + 1];
__device__ unsigned int g_barc[8];                // monotonic barrier counters (replay-safe)

__device__ __forceinline__ unsigned int f2sort(float f) {
    unsigned int u = __float_as_uint(f);
    return (u & 0x80000000u) ? ~u : (u | 0x80000000u);
}

// Grid barrier: monotonic counter + generation arithmetic. All NBLK blocks are
// co-resident (128 <= 148 SMs), so spinning cannot deadlock. Counter only ever
// increments, so it is correct across CUDA-graph replays without any reset.
__device__ __forceinline__ void gbar(int id) {
    __syncthreads();
    if (threadIdx.x == 0) {
        __threadfence();
        unsigned int old = atomicAdd(&g_barc[id], 1u);
        unsigned int target = (old / NBLK + 1u) * NBLK;
        while (atomicAdd(&g_barc[id], 0u) < target) { }
    }
    __syncthreads();
}

// paired block-wide scan helper (256 threads, double2); returns inclusive, sets total
__device__ __forceinline__ double2 bscan2(double2 v, double2& total) {
    __shared__ double sx[8], sy[8];
    __shared__ double stx, sty;
    __syncthreads();
    int t = threadIdx.x, lane = t & 31, wp = t >> 5;
    double x = v.x, y = v.y;
#pragma unroll
    for (int o = 1; o < 32; o <<= 1) {
        double nx = __shfl_up_sync(0xffffffffu, x, o);
        double ny = __shfl_up_sync(0xffffffffu, y, o);
        if (lane >= o) { x += nx; y += ny; }
    }
    if (lane == 31) { sx[wp] = x; sy[wp] = y; }
    __syncthreads();
    if (t == 0) {
        double rxx = 0.0, ryy = 0.0;
#pragma unroll
        for (int i2 = 0; i2 < 8; i2++) {
            double tx = sx[i2], ty = sy[i2];
            sx[i2] = rxx; sy[i2] = ryy;
            rxx += tx; ryy += ty;
        }
        stx = rxx; sty = ryy;
    }
    __syncthreads();
    total = make_double2(stx, sty);
    return make_double2(x + sx[wp], y + sy[wp]);
}

__global__ __launch_bounds__(NTHR, 1)
void gat_fused(const float* __restrict__ graph,
               const float* __restrict__ W,
               const float* __restrict__ a,
               float* __restrict__ out) {
    __shared__ float sW[F * F];
    __shared__ float sa[2 * F];
    __shared__ unsigned long long sk[256];

    int t = threadIdx.x;
    int blk = blockIdx.x;

    // ============ Phase 1: ltg = graph @ W + scalars (4 threads/row) =========
    for (int i = t; i < F * F; i += NTHR) sW[i] = W[i];
    if (t < 2 * F) sa[t] = a[t];
    __syncthreads();

    {
        int row = blk * 64 + (t >> 2);
        int fs = (t & 3) * 16;

        float acc[16];
#pragma unroll
        for (int f = 0; f < 16; f++) acc[f] = 0.f;

        const float4* g4 = reinterpret_cast<const float4*>(graph + (size_t)row * F);
#pragma unroll
        for (int k4i = 0; k4i < F / 4; k4i++) {
            float4 g = __ldg(&g4[k4i]);
            float gv[4] = {g.x, g.y, g.z, g.w};
#pragma unroll
            for (int kk = 0; kk < 4; kk++) {
                float gk = gv[kk];
                const float4* wr = reinterpret_cast<const float4*>(&sW[(k4i * 4 + kk) * F + fs]);
#pragma unroll
                for (int f4 = 0; f4 < 4; f4++) {
                    float4 w = wr[f4];
                    acc[f4 * 4 + 0] += gk * w.x;
                    acc[f4 * 4 + 1] += gk * w.y;
                    acc[f4 * 4 + 2] += gk * w.z;
                    acc[f4 * 4 + 3] += gk * w.w;
                }
            }
        }

        float ss = 0.f, sd = 0.f;
#pragma unroll
        for (int f = 0; f < 16; f++) {
            ss += acc[f] * sa[fs + f];
            sd += acc[f] * sa[F + fs + f];
        }
        ss += __shfl_xor_sync(0xffffffffu, ss, 1);
        ss += __shfl_xor_sync(0xffffffffu, ss, 2);
        sd += __shfl_xor_sync(0xffffffffu, sd, 1);
        sd += __shfl_xor_sync(0xffffffffu, sd, 2);

        float4* lo = reinterpret_cast<float4*>(g_ltg + (size_t)row * F + fs);
#pragma unroll
        for (int f4 = 0; f4 < 4; f4++)
            lo[f4] = make_float4(acc[f4 * 4 + 0], acc[f4 * 4 + 1],
                                 acc[f4 * 4 + 2], acc[f4 * 4 + 3]);

        if ((t & 3) == 0) {
            g_ssrc[row] = ss;
            g_sdst[row] = sd;
            g_P[row]  = expf(ss);
            g_p[row]  = expf(0.2f * ss);
            g_Qs[row] = expf(sd);
            g_qs[row] = expf(0.2f * sd);
            g_key[row] = ((unsigned long long)f2sort(sd) << 32) | (unsigned int)row;
        }
    }
    gbar(0);

    // ============ Phase 2: bitonic sort of 256-key tiles (blocks 0..31) ======
    if (blk < TILES) {
        sk[t] = g_key[blk * 256 + t];
        __syncthreads();
#pragma unroll
        for (int k = 2; k <= 256; k <<= 1) {
#pragma unroll
            for (int j = k >> 1; j > 0; j >>= 1) {
                int p = t ^ j;
                unsigned long long av = sk[t], bv = sk[p];
                if (p > t) {
                    bool up = ((t & k) == 0);
                    if ((av > bv) == up) { sk[t] = bv; sk[p] = av; }
                }
                __syncthreads();
            }
        }
        g_tkey[blk][t] = sk[t];
    }
    gbar(1);

    // ============ Phase 3: rank 64 keys/block via tile binary search =========
    {
        int i = blk * 64 + (t & 63);
        unsigned long long mykey = g_key[i];
        int rank = 0;
#pragma unroll 1
        for (int s = 0; s < TILES; s++) {
            __syncthreads();
            sk[t] = g_tkey[s][t];
            __syncthreads();
            if (t < 64) {
                int lo = 0, hi = 256;
#pragma unroll
                for (int st = 0; st < 9; st++) {
                    if (lo < hi) {
                        int mid = (lo + hi) >> 1;
                        if (sk[mid] < mykey) lo = mid + 1; else hi = mid;
                    }
                }
                rank += lo;
            }
        }
        if (t < 64) {
            g_perm[rank] = i;
            g_sorted[rank] = g_sdst[i];
        }
    }
    gbar(2);

    // ============ Phase 4: chunk totals (8 chunks/block, 2 passes) ===========
    {
        int f = t & 63;
#pragma unroll 1
        for (int pass = 0; pass < 2; pass++) {
            int chunk = blk * 8 + pass * 4 + (t >> 6);
            int kbase = chunk * CSZ;
            double sq = 0.0, sQ = 0.0, ssq = 0.0, ssQ = 0.0;
#pragma unroll
            for (int kk = 0; kk < CSZ; kk++) {
                int j = g_perm[kbase + kk];
                float q = g_qs[j], Q = g_Qs[j];
                float l = g_ltg[(size_t)j * F + f];
                sq += (double)(q * l);
                sQ += (double)(Q * l);
                if (f == 0) { ssq += (double)q; ssQ += (double)Q; }
            }
            g_ctq[f][chunk] = sq;
            g_ctQ[f][chunk] = sQ;
            if (f == 0) { g_ctq[64][chunk] = ssq; g_ctQ[64][chunk] = ssQ; }
        }
    }
    gbar(3);

    // ============ Phase 5: scan 1024 chunk totals per column (blocks 0..64) ==
    if (blk <= 64) {
        int f = blk;
        double vq[4], vQ[4];
#pragma unroll
        for (int r = 0; r < 4; r++) {
            vq[r] = g_ctq[f][t * 4 + r];
            vQ[r] = g_ctQ[f][t * 4 + r];
        }
        double pq[4], pQ[4], aq = 0.0, aQ = 0.0;
#pragma unroll
        for (int r = 0; r < 4; r++) {
            pq[r] = aq; aq += vq[r];
            pQ[r] = aQ; aQ += vQ[r];
        }
        double2 tot;
        double2 inc = bscan2(make_double2(aq, aQ), tot);
        double offq = inc.x - aq, offQ = inc.y - aQ;
#pragma unroll
        for (int r = 0; r < 4; r++) {
            g_coq[f][t * 4 + r] = offq + pq[r];
            g_coQ[f][t * 4 + r] = offQ + pQ[r];
        }
        if (t == 255) { g_totq[f] = tot.x; g_totQ[f] = tot.y; }
    }
    gbar(4);

    // ============ Phase 6: in-chunk serial scans, coalesced writes ===========
    {
        int f = t & 63;
#pragma unroll 1
        for (int pass = 0; pass < 2; pass++) {
            int chunk = blk * 8 + pass * 4 + (t >> 6);
            int kbase = chunk * CSZ;
            double rq = g_coq[f][chunk], rQ = g_coQ[f][chunk];
            double totQ = g_totQ[f];
            double rqs = 0.0, rQs = 0.0, totQs = 0.0;
            if (f == 0) {
                rqs = g_coq[64][chunk]; rQs = g_coQ[64][chunk]; totQs = g_totQ[64];
            }
#pragma unroll
            for (int kk = 0; kk < CSZ; kk++) {
                int k = kbase + kk;
                int j = g_perm[k];
                float q = g_qs[j], Q = g_Qs[j];
                float l = g_ltg[(size_t)j * F + f];
                g_Preq[(size_t)k * F + f] = (float)rq;
                g_SufQ[(size_t)k * F + f] = (float)(totQ - rQ);
                rq += (double)(q * l);
                rQ += (double)(Q * l);
                if (f == 0) {
                    g_Preqs[k] = (float)rqs;
                    g_SufQs[k] = (float)(totQs - rQs);
                    rqs += (double)q;
                    rQs += (double)Q;
                }
            }
            if (chunk == CHN - 1) {
                g_Preq[(size_t)N * F + f] = (float)rq;
                g_SufQ[(size_t)N * F + f] = 0.f;
                if (f == 0) { g_Preqs[N] = (float)rqs; g_SufQs[N] = 0.f; }
            }
        }
    }
    gbar(5);

    // ============ Phase 7: binary-search rank (14 steps) + combine ===========
    {
        __shared__ int   sc[64];
        __shared__ float sP[64], sp[64], sZ[64];
        int base = blk * 64;

        if (t < 64) {
            int row = base + t;
            float target = -g_ssrc[row];
            int lo = 0, hi = N;
#pragma unroll
            for (int step = 0; step < 14; step++) {
                if (lo < hi) {
                    int mid = (lo + hi) >> 1;
                    if (g_sorted[mid] < target) lo = mid + 1; else hi = mid;
                }
            }
            int c = lo;
            float P = g_P[row], p = g_p[row];
            float Z = P * g_SufQs[c] + p * g_Preqs[c];
            sc[t] = c; sP[t] = P; sp[t] = p; sZ[t] = 1.0f / Z;
        }
        __syncthreads();

        int f = t & 63;
        int rsub = t >> 6;
#pragma unroll
        for (int it = 0; it < 16; it++) {
            int rl = it * 4 + rsub;
            int c = sc[rl];
            float val = (sP[rl] * g_SufQ[(size_t)c * F + f] +
                         sp[rl] * g_Preq[(size_t)c * F + f]) * sZ[rl];
            out[(size_t)(base + rl) * F + f] = val;
        }
    }
}

// ---------------- launch ----------------
extern "C" void kernel_launch(void* const* d_in, const int* in_sizes, int n_in,
                              void* d_out, int out_size) {
    const float* graph = (const float*)d_in[0];
    const float* W     = (const float*)d_in[1];
    const float* a     = (const float*)d_in[2];
    float* out = (float*)d_out;

    gat_fused<<<NBLK, NTHR>>>(graph, W, a, out);
}

// round 10
// speedup vs baseline: 1.4450x; 1.4450x over previous
#include <cuda_runtime.h>
#include <cuda_bf16.h>

#define N 8192
#define F 64
#define TILES 32           // sorted key tiles of 256
#define TSZ 256
#define CHN 1024           // scan chunks
#define CSZ 8              // ranks per chunk
#define NBLK 128
#define NTHR 512

typedef unsigned long long u64;

// ---------------- scratch (no allocations allowed) ----------------
__device__ float g_ltg[N * F];
__device__ float g_ssrc[N];
__device__ float g_sdst[N];
__device__ float g_P[N];
__device__ float g_p[N];
__device__ float g_Qs[N];
__device__ float g_qs[N];
__device__ u64   g_key[N];            // (sortable(sdst)<<32)|idx — unique
__device__ u64   g_tkey[TILES][TSZ];  // per-tile sorted keys (flat-contiguous)
__device__ int   g_perm[N];
__device__ float g_sorted[N];
__device__ double g_ctq[72][CHN];     // chunk totals, row 64 = scalar
__device__ double g_ctQ[72][CHN];
__device__ double g_coq[72][CHN];     // exclusive chunk offsets
__device__ double g_coQ[72][CHN];
__device__ double g_totq[72];
__device__ double g_totQ[72];
__device__ float g_SufQ[(N + 1) * F];
__device__ float g_Preq[(N + 1) * F];
__device__ float g_SufQs[N + 1];
__device__ float g_Preqs[N + 1];
__device__ unsigned int g_barc[8];    // monotonic barrier counters (replay-safe)

__device__ __forceinline__ unsigned int f2sort(float f) {
    unsigned int u = __float_as_uint(f);
    return (u & 0x80000000u) ? ~u : (u | 0x80000000u);
}

// Grid barrier: monotonic counter + generation arithmetic; poll via volatile
// load (no RMW hammering). 128 blocks, launch_bounds(...,1) -> all co-resident.
__device__ __forceinline__ void gbar(int id) {
    __syncthreads();
    if (threadIdx.x == 0) {
        __threadfence();
        unsigned int old = atomicAdd(&g_barc[id], 1u);
        unsigned int target = (old / NBLK + 1u) * NBLK;
        volatile unsigned int* p = &g_barc[id];
        while (*p < target) { __nanosleep(64); }
        __threadfence();
    }
    __syncthreads();
}

__global__ __launch_bounds__(NTHR, 1)
void gat_fused(const float* __restrict__ graph,
               const float* __restrict__ W,
               const float* __restrict__ a,
               float* __restrict__ out) {
    // 16KB shared buffer reused: phase1 sW (16KB) / phase2 sort (4KB) / phase3 stage (16KB)
    __shared__ __align__(16) unsigned char s_buf[16384];
    __shared__ float sa[2 * F];
    __shared__ int   sRank[64];
    __shared__ int   sc[64];
    __shared__ float sP[64], sp[64], sZ[64];
    __shared__ double ssx[16], ssy[16];
    __shared__ double sstx, ssty;

    int t = threadIdx.x;
    int blk = blockIdx.x;

    // ============ Phase 1: ltg = graph @ W + scalars (8 threads/row) =========
    {
        float* sW = reinterpret_cast<float*>(s_buf);
        for (int i = t; i < F * F; i += NTHR) sW[i] = W[i];
        if (t < 2 * F) sa[t] = a[t];
        __syncthreads();

        int row = blk * 64 + (t >> 3);
        int fs = (t & 7) * 8;

        float acc[8];
#pragma unroll
        for (int f = 0; f < 8; f++) acc[f] = 0.f;

        const float4* g4 = reinterpret_cast<const float4*>(graph + (size_t)row * F);
#pragma unroll
        for (int k4i = 0; k4i < F / 4; k4i++) {
            float4 g = __ldg(&g4[k4i]);
            float gv[4] = {g.x, g.y, g.z, g.w};
#pragma unroll
            for (int kk = 0; kk < 4; kk++) {
                float gk = gv[kk];
                const float4* wr = reinterpret_cast<const float4*>(&sW[(k4i * 4 + kk) * F + fs]);
#pragma unroll
                for (int f4 = 0; f4 < 2; f4++) {
                    float4 w = wr[f4];
                    acc[f4 * 4 + 0] += gk * w.x;
                    acc[f4 * 4 + 1] += gk * w.y;
                    acc[f4 * 4 + 2] += gk * w.z;
                    acc[f4 * 4 + 3] += gk * w.w;
                }
            }
        }

        float ss = 0.f, sd = 0.f;
#pragma unroll
        for (int f = 0; f < 8; f++) {
            ss += acc[f] * sa[fs + f];
            sd += acc[f] * sa[F + fs + f];
        }
        ss += __shfl_xor_sync(0xffffffffu, ss, 1);
        ss += __shfl_xor_sync(0xffffffffu, ss, 2);
        ss += __shfl_xor_sync(0xffffffffu, ss, 4);
        sd += __shfl_xor_sync(0xffffffffu, sd, 1);
        sd += __shfl_xor_sync(0xffffffffu, sd, 2);
        sd += __shfl_xor_sync(0xffffffffu, sd, 4);

        float4* lo = reinterpret_cast<float4*>(g_ltg + (size_t)row * F + fs);
        lo[0] = make_float4(acc[0], acc[1], acc[2], acc[3]);
        lo[1] = make_float4(acc[4], acc[5], acc[6], acc[7]);

        if ((t & 7) == 0) {
            g_ssrc[row] = ss;
            g_sdst[row] = sd;
            g_P[row]  = expf(ss);
            g_p[row]  = expf(0.2f * ss);
            g_Qs[row] = expf(sd);
            g_qs[row] = expf(0.2f * sd);
            g_key[row] = ((u64)f2sort(sd) << 32) | (unsigned int)row;
        }
    }
    gbar(0);

    // ============ Phase 2: bitonic sort, 2 tiles of 256 per block (blk<16) ===
    if (blk < 16) {
        u64* sk = reinterpret_cast<u64*>(s_buf);
        int tl = t & 255;
        int th = t >> 8;            // 0/1: which tile half
        u64* s = sk + th * 256;
        int tile = blk * 2 + th;
        s[tl] = g_key[tile * 256 + tl];
        __syncthreads();
#pragma unroll
        for (int k = 2; k <= 256; k <<= 1) {
#pragma unroll
            for (int j = k >> 1; j > 0; j >>= 1) {
                int p = tl ^ j;
                u64 av = s[tl], bv = s[p];
                if (p > tl) {
                    bool up = ((tl & k) == 0);
                    if ((av > bv) == up) { s[tl] = bv; s[p] = av; }
                }
                __syncthreads();
            }
        }
        g_tkey[tile][tl] = s[tl];
    }
    gbar(1);

    // ============ Phase 3: rank — 2048 (key,tile) tasks, all threads search ==
    {
        u64* tb = reinterpret_cast<u64*>(s_buf);  // 2048 u64 = 16KB
        const u64* tkf = &g_tkey[0][0];
        int ki = t & 63;
        int tloc = t >> 6;          // 0..7: tile within round
        u64 mykey = g_key[blk * 64 + ki];
        if (t < 64) sRank[t] = 0;

#pragma unroll 1
        for (int round = 0; round < 4; round++) {
#pragma unroll
            for (int r = 0; r < 4; r++)
                tb[r * 512 + t] = tkf[round * 2048 + r * 512 + t];
            __syncthreads();

            const u64* tile = tb + tloc * 256;
            int lo = 0, hi = 256;
#pragma unroll
            for (int st = 0; st < 9; st++) {
                if (lo < hi) {
                    int mid = (lo + hi) >> 1;
                    if (tile[mid] < mykey) lo = mid + 1; else hi = mid;
                }
            }
            atomicAdd(&sRank[ki], lo);
            __syncthreads();
        }
        if (t < 64) {
            int i = blk * 64 + t;
            int rank = sRank[t];
            g_perm[rank] = i;
            g_sorted[rank] = g_sdst[i];
        }
    }
    gbar(2);

    // ============ Phase 4: chunk totals (8 chunks/block, one pass) ===========
    {
        int f = t & 63;
        int chunk = blk * 8 + (t >> 6);
        int kbase = chunk * CSZ;
        double sq = 0.0, sQ = 0.0, ssq = 0.0, ssQ = 0.0;
#pragma unroll
        for (int kk = 0; kk < CSZ; kk++) {
            int j = g_perm[kbase + kk];
            float q = g_qs[j], Q = g_Qs[j];
            float l = g_ltg[(size_t)j * F + f];
            sq += (double)(q * l);
            sQ += (double)(Q * l);
            if (f == 0) { ssq += (double)q; ssQ += (double)Q; }
        }
        g_ctq[f][chunk] = sq;
        g_ctQ[f][chunk] = sQ;
        if (f == 0) { g_ctq[64][chunk] = ssq; g_ctQ[64][chunk] = ssQ; }
    }
    gbar(3);

    // ============ Phase 5: scan 1024 chunk totals per column (blk<=64) =======
    if (blk <= 64) {
        int f = blk;
        double v0q = g_ctq[f][2 * t],     v0Q = g_ctQ[f][2 * t];
        double v1q = g_ctq[f][2 * t + 1], v1Q = g_ctQ[f][2 * t + 1];
        double aq = v0q + v1q, aQ = v0Q + v1Q;

        // 512-thread paired inclusive scan of (aq, aQ)
        int lane = t & 31, wp = t >> 5;
        double x = aq, y = aQ;
#pragma unroll
        for (int o = 1; o < 32; o <<= 1) {
            double nx = __shfl_up_sync(0xffffffffu, x, o);
            double ny = __shfl_up_sync(0xffffffffu, y, o);
            if (lane >= o) { x += nx; y += ny; }
        }
        if (lane == 31) { ssx[wp] = x; ssy[wp] = y; }
        __syncthreads();
        if (t == 0) {
            double rxx = 0.0, ryy = 0.0;
#pragma unroll
            for (int i2 = 0; i2 < 16; i2++) {
                double tx = ssx[i2], ty = ssy[i2];
                ssx[i2] = rxx; ssy[i2] = ryy;
                rxx += tx; ryy += ty;
            }
            sstx = rxx; ssty = ryy;
        }
        __syncthreads();
        double incx = x + ssx[wp];
        double incy = y + ssy[wp];
        double offq = incx - aq, offQ = incy - aQ;
        g_coq[f][2 * t] = offq;       g_coq[f][2 * t + 1] = offq + v0q;
        g_coQ[f][2 * t] = offQ;       g_coQ[f][2 * t + 1] = offQ + v0Q;
        if (t == 0) { g_totq[f] = sstx; g_totQ[f] = ssty; }
    }
    gbar(4);

    // ============ Phase 6: in-chunk serial scans, coalesced writes ===========
    {
        int f = t & 63;
        int chunk = blk * 8 + (t >> 6);
        int kbase = chunk * CSZ;
        double rq = g_coq[f][chunk], rQ = g_coQ[f][chunk];
        double totQ = g_totQ[f];
        double rqs = 0.0, rQs = 0.0, totQs = 0.0;
        if (f == 0) {
            rqs = g_coq[64][chunk]; rQs = g_coQ[64][chunk]; totQs = g_totQ[64];
        }
#pragma unroll
        for (int kk = 0; kk < CSZ; kk++) {
            int k = kbase + kk;
            int j = g_perm[k];
            float q = g_qs[j], Q = g_Qs[j];
            float l = g_ltg[(size_t)j * F + f];
            g_Preq[(size_t)k * F + f] = (float)rq;
            g_SufQ[(size_t)k * F + f] = (float)(totQ - rQ);
            rq += (double)(q * l);
            rQ += (double)(Q * l);
            if (f == 0) {
                g_Preqs[k] = (float)rqs;
                g_SufQs[k] = (float)(totQs - rQs);
                rqs += (double)q;
                rQs += (double)Q;
            }
        }
        if (chunk == CHN - 1) {
            g_Preq[(size_t)N * F + f] = (float)rq;
            g_SufQ[(size_t)N * F + f] = 0.f;
            if (f == 0) { g_Preqs[N] = (float)rqs; g_SufQs[N] = 0.f; }
        }
    }
    gbar(5);

    // ============ Phase 7: binary-search rank (14 steps) + combine ===========
    {
        int base = blk * 64;
        if (t < 64) {
            int row = base + t;
            float target = -g_ssrc[row];
            int lo = 0, hi = N;
#pragma unroll
            for (int step = 0; step < 14; step++) {
                if (lo < hi) {
                    int mid = (lo + hi) >> 1;
                    if (g_sorted[mid] < target) lo = mid + 1; else hi = mid;
                }
            }
            int c = lo;
            float P = g_P[row], p = g_p[row];
            float Z = P * g_SufQs[c] + p * g_Preqs[c];
            sc[t] = c; sP[t] = P; sp[t] = p; sZ[t] = 1.0f / Z;
        }
        __syncthreads();

        int f = t & 63;
        int rsub = t >> 6;   // 0..7
#pragma unroll
        for (int it = 0; it < 8; it++) {
            int rl = it * 8 + rsub;
            int c = sc[rl];
            float val = (sP[rl] * g_SufQ[(size_t)c * F + f] +
                         sp[rl] * g_Preq[(size_t)c * F + f]) * sZ[rl];
            out[(size_t)(base + rl) * F + f] = val;
        }
    }
}

// ---------------- launch ----------------
extern "C" void kernel_launch(void* const* d_in, const int* in_sizes, int n_in,
                              void* d_out, int out_size) {
    const float* graph = (const float*)d_in[0];
    const float* W     = (const float*)d_in[1];
    const float* a     = (const float*)d_in[2];
    float* out = (float*)d_out;

    gat_fused<<<NBLK, NTHR>>>(graph, W, a, out);
}

// round 12
// speedup vs baseline: 1.5096x; 1.0447x over previous
#include <cuda_runtime.h>
#include <cuda_bf16.h>

#define N 8192
#define F 64
#define TILES 32           // sorted key tiles of 256
#define TSZ 256
#define CHN 1024           // scan chunks
#define CSZ 8              // ranks per chunk
#define NBLK 128
#define NTHR 512

typedef unsigned long long u64;

// ---------------- scratch (no allocations allowed) ----------------
__device__ float g_ltg[N * F];
__device__ float g_ssrc[N];
__device__ float g_sdst[N];
__device__ float g_P[N];
__device__ float g_p[N];
__device__ float g_Qs[N];
__device__ float g_qs[N];
__device__ u64   g_key[N];            // (sortable(sdst)<<32)|idx — unique
__device__ u64   g_tkey[TILES][TSZ];  // per-tile sorted keys (flat-contiguous)
__device__ int   g_perm[N];
__device__ float g_sorted[N + 32];    // sdst ascending; +32 pad of +inf
__device__ float g_ctq[CHN][72];      // chunk totals (q side); col 64 = scalar
__device__ float g_ctQ[CHN][72];
__device__ float g_coq[CHN + 1][72];  // exclusive chunk offsets; row CHN = totals
__device__ float g_coQ[CHN + 1][72];
__device__ unsigned int g_barc[8];    // monotonic barrier counters (replay-safe)

__device__ __forceinline__ unsigned int f2sort(float f) {
    unsigned int u = __float_as_uint(f);
    return (u & 0x80000000u) ? ~u : (u | 0x80000000u);
}

// Grid barrier: monotonic counter + generation arithmetic; volatile poll.
__device__ __forceinline__ void gbar(int id) {
    __syncthreads();
    if (threadIdx.x == 0) {
        __threadfence();
        unsigned int old = atomicAdd(&g_barc[id], 1u);
        unsigned int target = (old / NBLK + 1u) * NBLK;
        volatile unsigned int* p = &g_barc[id];
        while (*p < target) { __nanosleep(64); }
        __threadfence();
    }
    __syncthreads();
}

__global__ __launch_bounds__(NTHR, 1)
void gat_fused(const float* __restrict__ graph,
               const float* __restrict__ W,
               const float* __restrict__ a,
               float* __restrict__ out) {
    // 16KB shared reuse: ph1 sW / ph2 sort / ph3 stage / ph6 splitters
    __shared__ __align__(16) unsigned char s_buf[16384];
    __shared__ float sa[2 * F];
    __shared__ int   sRank[64];
    __shared__ float ssx[16], ssy[16];

    int t = threadIdx.x;
    int blk = blockIdx.x;
    int lane = t & 31;

    // ============ Phase 1: ltg = graph @ W + scalars (8 threads/row) =========
    {
        float* sW = reinterpret_cast<float*>(s_buf);
        for (int i = t; i < F * F; i += NTHR) sW[i] = W[i];
        if (t < 2 * F) sa[t] = a[t];
        // +inf padding for the phase-6 ballot probe
        if (blk == NBLK - 1 && t < 32) g_sorted[N + t] = __int_as_float(0x7f800000);
        __syncthreads();

        int row = blk * 64 + (t >> 3);
        int fs = (t & 7) * 8;

        float acc[8];
#pragma unroll
        for (int f = 0; f < 8; f++) acc[f] = 0.f;

        const float4* g4 = reinterpret_cast<const float4*>(graph + (size_t)row * F);
#pragma unroll
        for (int k4i = 0; k4i < F / 4; k4i++) {
            float4 g = __ldg(&g4[k4i]);
            float gv[4] = {g.x, g.y, g.z, g.w};
#pragma unroll
            for (int kk = 0; kk < 4; kk++) {
                float gk = gv[kk];
                const float4* wr = reinterpret_cast<const float4*>(&sW[(k4i * 4 + kk) * F + fs]);
#pragma unroll
                for (int f4 = 0; f4 < 2; f4++) {
                    float4 w = wr[f4];
                    acc[f4 * 4 + 0] += gk * w.x;
                    acc[f4 * 4 + 1] += gk * w.y;
                    acc[f4 * 4 + 2] += gk * w.z;
                    acc[f4 * 4 + 3] += gk * w.w;
                }
            }
        }

        float ss = 0.f, sd = 0.f;
#pragma unroll
        for (int f = 0; f < 8; f++) {
            ss += acc[f] * sa[fs + f];
            sd += acc[f] * sa[F + fs + f];
        }
        ss += __shfl_xor_sync(0xffffffffu, ss, 1);
        ss += __shfl_xor_sync(0xffffffffu, ss, 2);
        ss += __shfl_xor_sync(0xffffffffu, ss, 4);
        sd += __shfl_xor_sync(0xffffffffu, sd, 1);
        sd += __shfl_xor_sync(0xffffffffu, sd, 2);
        sd += __shfl_xor_sync(0xffffffffu, sd, 4);

        float4* lo = reinterpret_cast<float4*>(g_ltg + (size_t)row * F + fs);
        lo[0] = make_float4(acc[0], acc[1], acc[2], acc[3]);
        lo[1] = make_float4(acc[4], acc[5], acc[6], acc[7]);

        if ((t & 7) == 0) {
            g_ssrc[row] = ss;
            g_sdst[row] = sd;
            g_P[row]  = expf(ss);
            g_p[row]  = expf(0.2f * ss);
            g_Qs[row] = expf(sd);
            g_qs[row] = expf(0.2f * sd);
            g_key[row] = ((u64)f2sort(sd) << 32) | (unsigned int)row;
        }
    }
    gbar(0);

    // ============ Phase 2: bitonic sort, 2 tiles of 256 per block (blk<16) ===
    if (blk < 16) {
        u64* sk = reinterpret_cast<u64*>(s_buf);
        int tl = t & 255;
        int th = t >> 8;
        u64* s = sk + th * 256;
        int tile = blk * 2 + th;
        s[tl] = g_key[tile * 256 + tl];
        __syncthreads();
#pragma unroll
        for (int k = 2; k <= 256; k <<= 1) {
#pragma unroll
            for (int j = k >> 1; j > 0; j >>= 1) {
                int p = tl ^ j;
                u64 av = s[tl], bv = s[p];
                if (p > tl) {
                    bool up = ((tl & k) == 0);
                    if ((av > bv) == up) { s[tl] = bv; s[p] = av; }
                }
                __syncthreads();
            }
        }
        g_tkey[tile][tl] = s[tl];
    }
    gbar(1);

    // ============ Phase 3: rank — 2048 (key,tile) tasks, all threads search ==
    {
        u64* tb = reinterpret_cast<u64*>(s_buf);  // 2048 u64 = 16KB
        const u64* tkf = &g_tkey[0][0];
        int ki = t & 63;
        int tloc = t >> 6;
        u64 mykey = g_key[blk * 64 + ki];
        if (t < 64) sRank[t] = 0;

#pragma unroll 1
        for (int round = 0; round < 4; round++) {
#pragma unroll
            for (int r = 0; r < 4; r++)
                tb[r * 512 + t] = tkf[round * 2048 + r * 512 + t];
            __syncthreads();

            const u64* tile = tb + tloc * 256;
            int lo = 0, hi = 256;
#pragma unroll
            for (int st = 0; st < 9; st++) {
                if (lo < hi) {
                    int mid = (lo + hi) >> 1;
                    if (tile[mid] < mykey) lo = mid + 1; else hi = mid;
                }
            }
            atomicAdd(&sRank[ki], lo);
            __syncthreads();
        }
        if (t < 64) {
            int i = blk * 64 + t;
            int rank = sRank[t];
            g_perm[rank] = i;
            g_sorted[rank] = g_sdst[i];
        }
    }
    gbar(2);

    // ============ Phase 4: fp32 chunk totals (8 chunks/block), coalesced =====
    {
        int f = t & 63;
        int chunk = blk * 8 + (t >> 6);
        int kbase = chunk * CSZ;
        float sq = 0.f, sQ = 0.f, ssq = 0.f, ssQ = 0.f;
#pragma unroll
        for (int kk = 0; kk < CSZ; kk++) {
            int j = g_perm[kbase + kk];
            float q = g_qs[j], Q = g_Qs[j];
            float l = g_ltg[(size_t)j * F + f];
            sq += q * l;
            sQ += Q * l;
            ssq += q; ssQ += Q;   // redundant across lanes; only f==0 writes
        }
        g_ctq[chunk][f] = sq;
        g_ctQ[chunk][f] = sQ;
        if (f == 0) { g_ctq[chunk][64] = ssq; g_ctQ[chunk][64] = ssQ; }
    }
    gbar(3);

    // ============ Phase 5: scan 1024 chunk totals per column (blk<=64) =======
    if (blk <= 64) {
        int f = blk;
        float v0q = g_ctq[2 * t][f],     v0Q = g_ctQ[2 * t][f];
        float v1q = g_ctq[2 * t + 1][f], v1Q = g_ctQ[2 * t + 1][f];
        float aq = v0q + v1q, aQ = v0Q + v1Q;

        int wp = t >> 5;
        float x = aq, y = aQ;
#pragma unroll
        for (int o = 1; o < 32; o <<= 1) {
            float nx = __shfl_up_sync(0xffffffffu, x, o);
            float ny = __shfl_up_sync(0xffffffffu, y, o);
            if (lane >= o) { x += nx; y += ny; }
        }
        if (lane == 31) { ssx[wp] = x; ssy[wp] = y; }
        __syncthreads();
        if (t < 16) {
            float wx = ssx[t], wy = ssy[t];
            float ix = wx, iy = wy;
#pragma unroll
            for (int o = 1; o < 16; o <<= 1) {
                float nx = __shfl_up_sync(0x0000ffffu, ix, o);
                float ny = __shfl_up_sync(0x0000ffffu, iy, o);
                if (t >= o) { ix += nx; iy += ny; }
            }
            ssx[t] = ix - wx;  // exclusive warp offset
            ssy[t] = iy - wy;
        }
        __syncthreads();
        float incx = x + ssx[wp];
        float incy = y + ssy[wp];
        float offq = incx - aq, offQ = incy - aQ;
        g_coq[2 * t][f] = offq;       g_coq[2 * t + 1][f] = offq + v0q;
        g_coQ[2 * t][f] = offQ;       g_coQ[2 * t + 1][f] = offQ + v0Q;
        if (t == 511) { g_coq[CHN][f] = incx; g_coQ[CHN][f] = incy; }
    }
    gbar(4);

    // ============ Phase 6: output — splitter search + on-the-fly prefix ======
    {
        float* sp = reinterpret_cast<float*>(s_buf);  // 256 splitters
        if (t < 256) sp[t] = g_sorted[t * 32 + 31];
        __syncthreads();

        int w = t >> 5;          // warp 0..15
        int base = blk * 64 + w * 4;

#pragma unroll 1
        for (int r = 0; r < 4; r++) {
            int row = base + r;
            float target = -g_ssrc[row];

            // splitter search (9 LDS steps) -> 32-block index b
            int lo = 0, hi = 256;
#pragma unroll
            for (int st = 0; st < 9; st++) {
                if (lo < hi) {
                    int mid = (lo + hi) >> 1;
                    if (sp[mid] < target) lo = mid + 1; else hi = mid;
                }
            }
            int b = lo;
            // one coalesced probe + ballot (padding makes b==256 safe)
            float v = g_sorted[b * 32 + lane];
            unsigned int m = __ballot_sync(0xffffffffu, v < target);
            int c = b * 32 + __popc(m);

            int chunk = c >> 3;
            int rem = c & 7;
            int kb = chunk * CSZ;

            // in-chunk partial (0..7 terms)
            float pre0 = 0.f, pre1 = 0.f, sf0 = 0.f, sf1 = 0.f, psq = 0.f, psQ = 0.f;
            for (int kk = 0; kk < rem; kk++) {
                int j = g_perm[kb + kk];
                float q = g_qs[j], Q = g_Qs[j];
                float l0 = g_ltg[(size_t)j * F + lane];
                float l1 = g_ltg[(size_t)j * F + 32 + lane];
                pre0 += q * l0; pre1 += q * l1;
                sf0  += Q * l0; sf1  += Q * l1;
                psq += q; psQ += Q;
            }

            float coq0 = g_coq[chunk][lane], coq1 = g_coq[chunk][32 + lane];
            float coQ0 = g_coQ[chunk][lane], coQ1 = g_coQ[chunk][32 + lane];
            float tQ0  = g_coQ[CHN][lane],   tQ1  = g_coQ[CHN][32 + lane];
            float cqs = g_coq[chunk][64];
            float cQs = g_coQ[chunk][64];
            float tQs = g_coQ[CHN][64];

            float P = g_P[row], p = g_p[row];
            float Z = P * (tQs - cQs - psQ) + p * (cqs + psq);
            float invZ = 1.0f / Z;

            float o0 = (P * (tQ0 - coQ0 - sf0) + p * (coq0 + pre0)) * invZ;
            float o1 = (P * (tQ1 - coQ1 - sf1) + p * (coq1 + pre1)) * invZ;
            out[(size_t)row * F + lane] = o0;
            out[(size_t)row * F + 32 + lane] = o1;
        }
    }
}

// ---------------- launch ----------------
extern "C" void kernel_launch(void* const* d_in, const int* in_sizes, int n_in,
                              void* d_out, int out_size) {
    const float* graph = (const float*)d_in[0];
    const float* W     = (const float*)d_in[1];
    const float* a     = (const float*)d_in[2];
    float* out = (float*)d_out;

    gat_fused<<<NBLK, NTHR>>>(graph, W, a, out);
}

// round 13
// speedup vs baseline: 1.6578x; 1.0982x over previous
#include <cuda_runtime.h>
#include <cuda_bf16.h>

#define N 8192
#define F 64
#define TILES 32           // sorted key tiles of 256
#define TSZ 256
#define CHN 2048           // scan chunks
#define CSZ 4              // ranks per chunk
#define NBLK 256
#define NTHR 512

typedef unsigned long long u64;

// ---------------- scratch (no allocations allowed) ----------------
__device__ float g_ltg[N * F];
__device__ float g_ssrc[N];
__device__ float g_sdst[N];
__device__ float g_P[N];
__device__ float g_p[N];
__device__ float g_Qs[N];
__device__ float g_qs[N];
__device__ u64   g_key[N];            // (sortable(sdst)<<32)|idx — unique
__device__ u64   g_tkey[TILES][TSZ];  // per-tile sorted keys (flat-contiguous)
__device__ int   g_perm[N];
__device__ float g_sorted[N + 32];    // sdst ascending; +32 pad of +inf
__device__ float g_ctqT[65][CHN];     // transposed chunk totals; row 64 = scalar
__device__ float g_ctQT[65][CHN];
__device__ float g_coq[CHN + 1][72];  // exclusive chunk offsets; row CHN = totals
__device__ float g_coQ[CHN + 1][72];
__device__ unsigned int g_barc[8];    // monotonic barrier counters (replay-safe)

__device__ __forceinline__ unsigned int f2sort(float f) {
    unsigned int u = __float_as_uint(f);
    return (u & 0x80000000u) ? ~u : (u | 0x80000000u);
}

// Grid barrier: monotonic counter + generation arithmetic; volatile poll.
// 256 blocks, launch_bounds(512,2) -> all co-resident (256 <= 148*2).
__device__ __forceinline__ void gbar(int id) {
    __syncthreads();
    if (threadIdx.x == 0) {
        __threadfence();
        unsigned int old = atomicAdd(&g_barc[id], 1u);
        unsigned int target = (old / NBLK + 1u) * NBLK;
        volatile unsigned int* p = &g_barc[id];
        while (*p < target) { __nanosleep(64); }
        __threadfence();
    }
    __syncthreads();
}

__global__ __launch_bounds__(NTHR, 2)
void gat_fused(const float* __restrict__ graph,
               const float* __restrict__ W,
               const float* __restrict__ a,
               float* __restrict__ out) {
    // 32KB shared reuse: ph1 sW(16K) / ph2 sort(4K) / ph3 stage(32K) / ph6 splitters(1K)
    __shared__ __align__(16) unsigned char s_buf[32768];
    __shared__ float sa[2 * F];
    __shared__ int   sRank[32];
    __shared__ float ssx[16], ssy[16];

    int t = threadIdx.x;
    int blk = blockIdx.x;
    int lane = t & 31;

    // ============ Phase 1: ltg = graph @ W + scalars (16 threads/row) ========
    {
        float* sW = reinterpret_cast<float*>(s_buf);
        for (int i = t; i < F * F; i += NTHR) sW[i] = W[i];
        if (t < 2 * F) sa[t] = a[t];
        if (blk == 0 && t < 32) g_sorted[N + t] = __int_as_float(0x7f800000);
        __syncthreads();

        int row = blk * 32 + (t >> 4);
        int fs = (t & 15) * 4;

        float acc[4] = {0.f, 0.f, 0.f, 0.f};

        const float4* g4 = reinterpret_cast<const float4*>(graph + (size_t)row * F);
#pragma unroll
        for (int k4i = 0; k4i < F / 4; k4i++) {
            float4 g = __ldg(&g4[k4i]);
            float gv[4] = {g.x, g.y, g.z, g.w};
#pragma unroll
            for (int kk = 0; kk < 4; kk++) {
                float gk = gv[kk];
                float4 w = *reinterpret_cast<const float4*>(&sW[(k4i * 4 + kk) * F + fs]);
                acc[0] += gk * w.x;
                acc[1] += gk * w.y;
                acc[2] += gk * w.z;
                acc[3] += gk * w.w;
            }
        }

        float ss = 0.f, sd = 0.f;
#pragma unroll
        for (int f = 0; f < 4; f++) {
            ss += acc[f] * sa[fs + f];
            sd += acc[f] * sa[F + fs + f];
        }
        ss += __shfl_xor_sync(0xffffffffu, ss, 1);
        ss += __shfl_xor_sync(0xffffffffu, ss, 2);
        ss += __shfl_xor_sync(0xffffffffu, ss, 4);
        ss += __shfl_xor_sync(0xffffffffu, ss, 8);
        sd += __shfl_xor_sync(0xffffffffu, sd, 1);
        sd += __shfl_xor_sync(0xffffffffu, sd, 2);
        sd += __shfl_xor_sync(0xffffffffu, sd, 4);
        sd += __shfl_xor_sync(0xffffffffu, sd, 8);

        *reinterpret_cast<float4*>(g_ltg + (size_t)row * F + fs) =
            make_float4(acc[0], acc[1], acc[2], acc[3]);

        if ((t & 15) == 0) {
            g_ssrc[row] = ss;
            g_sdst[row] = sd;
            g_P[row]  = expf(ss);
            g_p[row]  = expf(0.2f * ss);
            g_Qs[row] = expf(sd);
            g_qs[row] = expf(0.2f * sd);
            g_key[row] = ((u64)f2sort(sd) << 32) | (unsigned int)row;
        }
    }
    gbar(0);

    // ============ Phase 2: bitonic sort, 2 tiles of 256 per block (blk<16) ===
    if (blk < 16) {
        u64* sk = reinterpret_cast<u64*>(s_buf);
        int tl = t & 255;
        int th = t >> 8;
        u64* s = sk + th * 256;
        int tile = blk * 2 + th;
        s[tl] = g_key[tile * 256 + tl];
        __syncthreads();
#pragma unroll
        for (int k = 2; k <= 256; k <<= 1) {
#pragma unroll
            for (int j = k >> 1; j > 0; j >>= 1) {
                int p = tl ^ j;
                u64 av = s[tl], bv = s[p];
                if (p > tl) {
                    bool up = ((tl & k) == 0);
                    if ((av > bv) == up) { s[tl] = bv; s[p] = av; }
                }
                __syncthreads();
            }
        }
        g_tkey[tile][tl] = s[tl];
    }
    gbar(1);

    // ============ Phase 3: rank — 32 keys x 32 tiles, 2 rounds of 16 staged ==
    {
        u64* tb = reinterpret_cast<u64*>(s_buf);  // 4096 u64 = 32KB
        const u64* tkf = &g_tkey[0][0];
        int ki = t & 31;                // key (lane); warp lanes -> distinct keys
        int tloc = t >> 5;              // tile slot 0..15 (constant per warp)
        u64 mykey = g_key[blk * 32 + ki];
        if (t < 32) sRank[t] = 0;

#pragma unroll 1
        for (int round = 0; round < 2; round++) {
#pragma unroll
            for (int r = 0; r < 8; r++)
                tb[r * 512 + t] = tkf[round * 4096 + r * 512 + t];
            __syncthreads();

            const u64* tile = tb + tloc * 256;
            int lo = 0, hi = 256;
#pragma unroll
            for (int st = 0; st < 9; st++) {
                if (lo < hi) {
                    int mid = (lo + hi) >> 1;
                    if (tile[mid] < mykey) lo = mid + 1; else hi = mid;
                }
            }
            atomicAdd(&sRank[ki], lo);
            __syncthreads();
        }
        if (t < 32) {
            int i = blk * 32 + t;
            int rank = sRank[t];
            g_perm[rank] = i;
            g_sorted[rank] = g_sdst[i];
        }
    }
    gbar(2);

    // ============ Phase 4: fp32 chunk totals (8 chunks/block, CSZ=4) =========
    {
        int f = t & 63;
        int chunk = blk * 8 + (t >> 6);
        int kbase = chunk * CSZ;
        float sq = 0.f, sQ = 0.f, ssq = 0.f, ssQ = 0.f;
#pragma unroll
        for (int kk = 0; kk < CSZ; kk++) {
            int j = g_perm[kbase + kk];
            float q = g_qs[j], Q = g_Qs[j];
            float l = g_ltg[(size_t)j * F + f];
            sq += q * l;
            sQ += Q * l;
            ssq += q; ssQ += Q;
        }
        g_ctqT[f][chunk] = sq;       // scattered stores (fire-and-forget)
        g_ctQT[f][chunk] = sQ;
        if (f == 0) { g_ctqT[64][chunk] = ssq; g_ctQT[64][chunk] = ssQ; }
    }
    gbar(3);

    // ============ Phase 5: scan 2048 chunk totals per column (blk<=64) =======
    if (blk <= 64) {
        int f = blk;
        float4 vq = *reinterpret_cast<const float4*>(&g_ctqT[f][4 * t]);  // coalesced
        float4 vQ = *reinterpret_cast<const float4*>(&g_ctQT[f][4 * t]);
        float aq = vq.x + vq.y + vq.z + vq.w;
        float aQ = vQ.x + vQ.y + vQ.z + vQ.w;

        int wp = t >> 5;
        float x = aq, y = aQ;
#pragma unroll
        for (int o = 1; o < 32; o <<= 1) {
            float nx = __shfl_up_sync(0xffffffffu, x, o);
            float ny = __shfl_up_sync(0xffffffffu, y, o);
            if (lane >= o) { x += nx; y += ny; }
        }
        if (lane == 31) { ssx[wp] = x; ssy[wp] = y; }
        __syncthreads();
        if (t < 16) {
            float wx = ssx[t], wy = ssy[t];
            float ix = wx, iy = wy;
#pragma unroll
            for (int o = 1; o < 16; o <<= 1) {
                float nx = __shfl_up_sync(0x0000ffffu, ix, o);
                float ny = __shfl_up_sync(0x0000ffffu, iy, o);
                if (t >= o) { ix += nx; iy += ny; }
            }
            ssx[t] = ix - wx;  // exclusive warp offset
            ssy[t] = iy - wy;
        }
        __syncthreads();
        float incx = x + ssx[wp];
        float incy = y + ssy[wp];
        float offq = incx - aq, offQ = incy - aQ;

        g_coq[4 * t + 0][f] = offq;
        g_coq[4 * t + 1][f] = offq + vq.x;
        g_coq[4 * t + 2][f] = offq + vq.x + vq.y;
        g_coq[4 * t + 3][f] = offq + vq.x + vq.y + vq.z;
        g_coQ[4 * t + 0][f] = offQ;
        g_coQ[4 * t + 1][f] = offQ + vQ.x;
        g_coQ[4 * t + 2][f] = offQ + vQ.x + vQ.y;
        g_coQ[4 * t + 3][f] = offQ + vQ.x + vQ.y + vQ.z;
        if (t == 511) { g_coq[CHN][f] = incx; g_coQ[CHN][f] = incy; }
    }
    gbar(4);

    // ============ Phase 6: output — splitter search + on-the-fly prefix ======
    {
        float* sp = reinterpret_cast<float*>(s_buf);  // 256 splitters
        if (t < 256) sp[t] = g_sorted[t * 32 + 31];
        __syncthreads();

        int w = t >> 5;              // warp 0..15, 2 rows each
        int base = blk * 32 + w * 2;

#pragma unroll 1
        for (int r = 0; r < 2; r++) {
            int row = base + r;
            float target = -g_ssrc[row];

            int lo = 0, hi = 256;
#pragma unroll
            for (int st = 0; st < 9; st++) {
                if (lo < hi) {
                    int mid = (lo + hi) >> 1;
                    if (sp[mid] < target) lo = mid + 1; else hi = mid;
                }
            }
            int b = lo;
            float v = g_sorted[b * 32 + lane];
            unsigned int m = __ballot_sync(0xffffffffu, v < target);
            int c = b * 32 + __popc(m);

            int chunk = c >> 2;
            int rem = c & 3;
            int kb = chunk * CSZ;

            float pre0 = 0.f, pre1 = 0.f, sf0 = 0.f, sf1 = 0.f, psq = 0.f, psQ = 0.f;
            for (int kk = 0; kk < rem; kk++) {
                int j = g_perm[kb + kk];
                float q = g_qs[j], Q = g_Qs[j];
                float l0 = g_ltg[(size_t)j * F + lane];
                float l1 = g_ltg[(size_t)j * F + 32 + lane];
                pre0 += q * l0; pre1 += q * l1;
                sf0  += Q * l0; sf1  += Q * l1;
                psq += q; psQ += Q;
            }

            float coq0 = g_coq[chunk][lane], coq1 = g_coq[chunk][32 + lane];
            float coQ0 = g_coQ[chunk][lane], coQ1 = g_coQ[chunk][32 + lane];
            float tQ0  = g_coQ[CHN][lane],   tQ1  = g_coQ[CHN][32 + lane];
            float cqs = g_coq[chunk][64];
            float cQs = g_coQ[chunk][64];
            float tQs = g_coQ[CHN][64];

            float P = g_P[row], p = g_p[row];
            float Z = P * (tQs - cQs - psQ) + p * (cqs + psq);
            float invZ = 1.0f / Z;

            float o0 = (P * (tQ0 - coQ0 - sf0) + p * (coq0 + pre0)) * invZ;
            float o1 = (P * (tQ1 - coQ1 - sf1) + p * (coq1 + pre1)) * invZ;
            out[(size_t)row * F + lane] = o0;
            out[(size_t)row * F + 32 + lane] = o1;
        }
    }
}

// ---------------- launch ----------------
extern "C" void kernel_launch(void* const* d_in, const int* in_sizes, int n_in,
                              void* d_out, int out_size) {
    const float* graph = (const float*)d_in[0];
    const float* W     = (const float*)d_in[1];
    const float* a     = (const float*)d_in[2];
    float* out = (float*)d_out;

    gat_fused<<<NBLK, NTHR>>>(graph, W, a, out);
}